// round 11
// baseline (speedup 1.0000x reference)
#include <cuda_runtime.h>

#define NTAGS 64
#define SOS_IDX 1
#define EOS_IDX 2
#define REF_TAG 3

static __device__ __forceinline__ unsigned long long pk2(float x, float y) {
    unsigned long long r;
    asm("mov.b64 %0, {%1, %2};" : "=l"(r) : "f"(x), "f"(y));
    return r;
}
static __device__ __forceinline__ void upk2(unsigned long long a, float &x, float &y) {
    asm("mov.b64 {%0, %1}, %2;" : "=f"(x), "=f"(y) : "l"(a));
}
static __device__ __forceinline__ unsigned long long fma2(unsigned long long a,
                                                          unsigned long long b,
                                                          unsigned long long c) {
    unsigned long long d;
    asm("fma.rn.f32x2 %0, %1, %2, %3;" : "=l"(d) : "l"(a), "l"(b), "l"(c));
    return d;
}
static __device__ __forceinline__ unsigned long long add2(unsigned long long a,
                                                          unsigned long long b) {
    unsigned long long d;
    asm("add.rn.f32x2 %0, %1, %2;" : "=l"(d) : "l"(a), "l"(b));
    return d;
}

__global__ void __launch_bounds__(128) crf_fwd_kernel(
    const float* __restrict__ h, const float* __restrict__ mask,
    const float* __restrict__ trans, float* __restrict__ out, int T, int B)
{
    const int tid = threadIdx.x;
    const int chain = tid >> 6;         // 0: warps 0-1 (SMSP 0,1), 1: warps 2-3 (SMSP 2,3)
    const int i = tid & 63;             // tag index within chain group
    const int warp = i >> 5;
    const int lane = i & 31;

    const int b = blockIdx.x + chain * gridDim.x;
    const bool active = (b < B);
    const int bsafe = active ? b : 0;

    __shared__ __align__(16) float sh_u[2][2][NTAGS];   // [chain][buf][tag]
    __shared__ float sh_red[2][2];                      // [chain][warp]
    __shared__ int sh_len[2];

    // ---- len = sum(mask[b,:]) once (mask is a prefix of ones) ----
    const float* mb = mask + (size_t)bsafe * T;
    {
        float msum = 0.0f;
        const float4* m4 = reinterpret_cast<const float4*>(mb);
        const int n4 = T >> 2;
        for (int k = i; k < n4; k += NTAGS) {
            float4 v = m4[k];
            msum += (v.x + v.y) + (v.z + v.w);
        }
        #pragma unroll
        for (int o = 16; o > 0; o >>= 1) msum += __shfl_xor_sync(0xffffffffu, msum, o);
        if (lane == 0) sh_red[chain][warp] = msum;
    }

    // E[i][j] = exp(trans[i][j]) packed as f32x2 (constant over t).
    // exp(-10000) underflows to exactly 0 -> masked transitions vanish.
    unsigned long long E2[NTAGS / 2];
    {
        const float4* tr = reinterpret_cast<const float4*>(trans + i * NTAGS);
        #pragma unroll
        for (int k = 0; k < NTAGS / 4; k++) {
            float4 t4 = tr[k];
            E2[2 * k]     = pk2(__expf(t4.x), __expf(t4.y));
            E2[2 * k + 1] = pk2(__expf(t4.z), __expf(t4.w));
        }
    }
    const float eeos = __expf(trans[EOS_IDX * NTAGS + i]);

    const float* hb = h + (size_t)bsafe * T * NTAGS + i;

    __syncthreads();
    const int len = active ? (int)(sh_red[chain][0] + sh_red[chain][1] + 0.5f) : 0;
    if (i == 0) sh_len[chain] = len;

    // raw prefetch buffers (depth 4)
    float rawh[4];
    #pragma unroll
    for (int k = 0; k < 4; k++) {
        int tp = (k < T) ? k : (T - 1);
        rawh[k] = hb[(size_t)tp * NTAGS];
    }

    // U(-1): 1 at SOS, 0 elsewhere.
    sh_u[chain][0][i] = (i == SOS_IDX) ? 1.0f : 0.0f;
    float myu = (i == SOS_IDX) ? 1.0f : 0.0f;
    int Esum = 0;
    float ehcur = __expf(rawh[0]);      // exp computed one full step ahead
    __syncthreads();
    const int lenmax = (sh_len[0] > sh_len[1]) ? sh_len[0] : sh_len[1];

    #pragma unroll 4
    for (int t = 0; t < lenmax; t++) {
        if (t < len) {                  // chain-uniform guard
            const float* up = sh_u[chain][t & 1];
            float* un = sh_u[chain][(t + 1) & 1];
            const float4* pv = reinterpret_cast<const float4*>(up);

            // --- issue all shared loads first: renorm scalar + 16 LDS.128 ---
            const unsigned int ub = __float_as_uint(up[REF_TAG]);
            float4 pa[16];
            #pragma unroll
            for (int k = 0; k < 16; k++) pa[k] = pv[k];

            // independent work overlapping LDS latency: h(t+4), exp(t+1)
            int tp = t + 4;
            tp = (tp < T) ? tp : (T - 1);   // clamped, always in-bounds
            float fresh = hb[(size_t)tp * NTAGS];
            float ehnext = __expf(rawh[(t + 1) & 3]);   // loaded at t-3
            rawh[t & 3] = fresh;
            const float eh = ehcur;
            ehcur = ehnext;

            // exact power-of-two renormalizer (ALU-only, off the dot path)
            int e = (int)((ub >> 23) & 0xffu) - 127;
            e = (ub == 0u) ? 0 : e;         // t==0: uref is exactly 0
            const float scale = __uint_as_float((unsigned)(127 - e) << 23);
            Esum += e;
            const float es = eh * scale;

            // w_i = dot(E_row_i, U_prev): 32 fma2, 8 independent accumulators
            unsigned long long acc[8];
            #pragma unroll
            for (int k = 0; k < 16; k++) {
                const int a0 = (k & 3) * 2;
                unsigned long long lo = fma2(E2[2 * k],     pk2(pa[k].x, pa[k].y),
                                             (k < 4) ? 0ull : acc[a0]);
                unsigned long long hi = fma2(E2[2 * k + 1], pk2(pa[k].z, pa[k].w),
                                             (k < 4) ? 0ull : acc[a0 + 1]);
                acc[a0] = lo; acc[a0 + 1] = hi;
            }
            unsigned long long sA = add2(add2(add2(acc[0], acc[2]), add2(acc[4], acc[6])),
                                         add2(add2(acc[1], acc[3]), add2(acc[5], acc[7])));
            float vx, vy;
            upk2(sA, vx, vy);
            const float w = vx + vy;

            const float u = es * w;         // U_i(t)
            un[i] = u;
            myu = u;
        }
        __syncthreads();                    // one plain barrier, both chains
    }

    // out[b] = Esum*ln2 + log( sum_i U_i * exp(trans[EOS,i]) )
    float term = myu * eeos;
    #pragma unroll
    for (int o = 16; o > 0; o >>= 1) term += __shfl_xor_sync(0xffffffffu, term, o);
    __syncthreads();                        // sh_red reuse safety
    if (lane == 0) sh_red[chain][warp] = term;
    __syncthreads();
    if (i == 0 && active) {
        out[b] = (float)Esum * 0.6931471805599453f +
                 __logf(sh_red[chain][0] + sh_red[chain][1]);
    }
}

extern "C" void kernel_launch(void* const* d_in, const int* in_sizes, int n_in,
                              void* d_out, int out_size) {
    const float* h     = (const float*)d_in[0];   // [B, T, 64]
    const float* mask  = (const float*)d_in[1];   // [B, T]
    const float* trans = (const float*)d_in[2];   // [64, 64]
    float* out = (float*)d_out;                   // [B]
    const int B = out_size;
    const int T = in_sizes[1] / B;
    const int grid = (B + 1) / 2;
    crf_fwd_kernel<<<grid, 128>>>(h, mask, trans, out, T, B);
}

// round 12
// speedup vs baseline: 1.9229x; 1.9229x over previous
#include <cuda_runtime.h>

#define NTAGS 64
#define SOS_IDX 1
#define EOS_IDX 2
#define REF_TAG 3
#define MAXB 1024
#define NWORKER 148

__device__ int g_len[MAXB];
__device__ int g_order[MAXB];
__device__ int g_ctr;

static __device__ __forceinline__ unsigned long long pk2(float x, float y) {
    unsigned long long r;
    asm("mov.b64 %0, {%1, %2};" : "=l"(r) : "f"(x), "f"(y));
    return r;
}
static __device__ __forceinline__ void upk2(unsigned long long a, float &x, float &y) {
    asm("mov.b64 {%0, %1}, %2;" : "=f"(x), "=f"(y) : "l"(a));
}
static __device__ __forceinline__ unsigned long long fma2(unsigned long long a,
                                                          unsigned long long b,
                                                          unsigned long long c) {
    unsigned long long d;
    asm("fma.rn.f32x2 %0, %1, %2, %3;" : "=l"(d) : "l"(a), "l"(b), "l"(c));
    return d;
}
static __device__ __forceinline__ unsigned long long add2(unsigned long long a,
                                                          unsigned long long b) {
    unsigned long long d;
    asm("add.rn.f32x2 %0, %1, %2;" : "=l"(d) : "l"(a), "l"(b));
    return d;
}

// ---- kernel 1: lengths (mask is a prefix of ones) ----
__global__ void __launch_bounds__(NTAGS) len_kernel(
    const float* __restrict__ mask, int T)
{
    const int b = blockIdx.x;
    const int i = threadIdx.x;
    const float4* m4 = reinterpret_cast<const float4*>(mask + (size_t)b * T);
    float msum = 0.0f;
    const int n4 = T >> 2;
    for (int k = i; k < n4; k += NTAGS) {
        float4 v = m4[k];
        msum += (v.x + v.y) + (v.z + v.w);
    }
    #pragma unroll
    for (int o = 16; o > 0; o >>= 1) msum += __shfl_xor_sync(0xffffffffu, msum, o);
    __shared__ float sh[2];
    if ((i & 31) == 0) sh[i >> 5] = msum;
    __syncthreads();
    if (i == 0) g_len[b] = (int)(sh[0] + sh[1] + 0.5f);
}

// ---- kernel 2: sort ids by length descending (bitonic, one block), reset ctr ----
__global__ void sort_kernel(int B, int n /* pow2 >= B */)
{
    extern __shared__ int smem_sort[];
    int* key = smem_sort;          // -len (ascending sort -> longest first)
    int* val = smem_sort + n;
    const int tid = threadIdx.x;
    if (tid < n) {
        key[tid] = (tid < B) ? -g_len[tid] : 0x7fffffff;
        val[tid] = tid;
    }
    __syncthreads();
    for (int k = 2; k <= n; k <<= 1) {
        for (int j = k >> 1; j > 0; j >>= 1) {
            int ixj = tid ^ j;
            if (ixj > tid && tid < n) {
                bool up = ((tid & k) == 0);
                int ka = key[tid], kb = key[ixj];
                if ((ka > kb) == up) {
                    key[tid] = kb; key[ixj] = ka;
                    int va = val[tid]; val[tid] = val[ixj]; val[ixj] = va;
                }
            }
            __syncthreads();
        }
    }
    if (tid < B) g_order[tid] = val[tid];
    if (tid == 0) g_ctr = 0;
}

// ---- kernel 3: persistent workers, longest chains first ----
__global__ void __launch_bounds__(NTAGS) crf_main_kernel(
    const float* __restrict__ h, const float* __restrict__ mask,
    const float* __restrict__ trans, float* __restrict__ out, int T, int B)
{
    const int i = threadIdx.x;          // one thread per tag
    const int warp = i >> 5;
    const int lane = i & 31;

    __shared__ __align__(16) float sh_u[2][NTAGS];
    __shared__ float sh_red[2];
    __shared__ int sh_idx;

    // E[i][j] = exp(trans[i][j]) packed as f32x2 (constant over all chains).
    // exp(-10000) underflows to exactly 0 -> masked transitions vanish.
    unsigned long long E2[NTAGS / 2];
    {
        const float4* tr = reinterpret_cast<const float4*>(trans + i * NTAGS);
        #pragma unroll
        for (int k = 0; k < NTAGS / 4; k++) {
            float4 t4 = tr[k];
            E2[2 * k]     = pk2(__expf(t4.x), __expf(t4.y));
            E2[2 * k + 1] = pk2(__expf(t4.z), __expf(t4.w));
        }
    }
    const float eeos = __expf(trans[EOS_IDX * NTAGS + i]);

    for (;;) {
        if (i == 0) sh_idx = atomicAdd(&g_ctr, 1);
        __syncthreads();
        const int idx = sh_idx;
        if (idx >= B) break;            // uniform exit
        const int b = g_order[idx];
        const int len = g_len[b];
        const float* hb = h + (size_t)b * T * NTAGS + i;

        // raw prefetch buffers (depth 4)
        float rawh[4];
        #pragma unroll
        for (int k = 0; k < 4; k++) {
            int tp = (k < T) ? k : (T - 1);
            rawh[k] = hb[(size_t)tp * NTAGS];
        }

        // U(-1): 1 at SOS, 0 elsewhere.
        sh_u[0][i] = (i == SOS_IDX) ? 1.0f : 0.0f;
        float myu = (i == SOS_IDX) ? 1.0f : 0.0f;
        int Esum = 0;
        float ehcur = __expf(rawh[0]);  // exp computed one full step ahead
        __syncthreads();

        #pragma unroll 4
        for (int t = 0; t < len; t++) {
            const float* up = sh_u[t & 1];
            float* un = sh_u[(t + 1) & 1];
            const float4* pv = reinterpret_cast<const float4*>(up);

            // issue all shared loads first: renorm scalar + 16 LDS.128
            const unsigned int ub = __float_as_uint(up[REF_TAG]);
            float4 pa[16];
            #pragma unroll
            for (int k = 0; k < 16; k++) pa[k] = pv[k];

            // independent work overlapping LDS latency: h(t+4), exp(t+1)
            int tp = t + 4;
            tp = (tp < T) ? tp : (T - 1);
            float fresh = hb[(size_t)tp * NTAGS];
            float ehnext = __expf(rawh[(t + 1) & 3]);   // loaded at t-3
            rawh[t & 3] = fresh;
            const float eh = ehcur;
            ehcur = ehnext;

            // exact power-of-two renormalizer (ALU-only, off the dot path)
            int e = (int)((ub >> 23) & 0xffu) - 127;
            e = (ub == 0u) ? 0 : e;         // t==0: uref is exactly 0
            const float scale = __uint_as_float((unsigned)(127 - e) << 23);
            Esum += e;
            const float es = eh * scale;

            // w_i = dot(E_row_i, U_prev): 32 fma2, 8 independent accumulators
            unsigned long long acc[8];
            #pragma unroll
            for (int k = 0; k < 16; k++) {
                const int a0 = (k & 3) * 2;
                unsigned long long lo = fma2(E2[2 * k],     pk2(pa[k].x, pa[k].y),
                                             (k < 4) ? 0ull : acc[a0]);
                unsigned long long hi = fma2(E2[2 * k + 1], pk2(pa[k].z, pa[k].w),
                                             (k < 4) ? 0ull : acc[a0 + 1]);
                acc[a0] = lo; acc[a0 + 1] = hi;
            }
            unsigned long long sA = add2(add2(add2(acc[0], acc[2]), add2(acc[4], acc[6])),
                                         add2(add2(acc[1], acc[3]), add2(acc[5], acc[7])));
            float vx, vy;
            upk2(sA, vx, vy);
            const float w = vx + vy;

            const float u = es * w;         // U_i(t)
            un[i] = u;
            myu = u;
            __syncthreads();                // single barrier per step
        }

        // out[b] = Esum*ln2 + log( sum_i U_i * exp(trans[EOS,i]) )
        float term = myu * eeos;
        #pragma unroll
        for (int o = 16; o > 0; o >>= 1) term += __shfl_xor_sync(0xffffffffu, term, o);
        __syncthreads();
        if (lane == 0) sh_red[warp] = term;
        __syncthreads();
        if (i == 0) {
            out[b] = (float)Esum * 0.6931471805599453f + __logf(sh_red[0] + sh_red[1]);
        }
        __syncthreads();                    // protect sh_u/sh_red before next chain
    }
}

extern "C" void kernel_launch(void* const* d_in, const int* in_sizes, int n_in,
                              void* d_out, int out_size) {
    const float* h     = (const float*)d_in[0];   // [B, T, 64]
    const float* mask  = (const float*)d_in[1];   // [B, T]
    const float* trans = (const float*)d_in[2];   // [64, 64]
    float* out = (float*)d_out;                   // [B]
    const int B = out_size;
    const int T = in_sizes[1] / B;
    int n = 1;
    while (n < B) n <<= 1;                        // pow2 for bitonic
    len_kernel<<<B, NTAGS>>>(mask, T);
    sort_kernel<<<1, n, 2 * n * sizeof(int)>>>(B, n);
    crf_main_kernel<<<NWORKER, NTAGS>>>(h, mask, trans, out, T, B);
}